// round 11
// baseline (speedup 1.0000x reference)
#include <cuda_runtime.h>
#include <cstdint>

// Reference = patchify ∘ depatchify == identity -> 256 MiB D2D copy.
//
// History (kernel time / DRAM-active):
//  R1: 4xfloat4/thread            74.0us / 82.5%
//  R2: CE memcpy                  84us dur — regression, SM path at LTS cap
//  R3: 8xfloat4 + .cs             75.6us / 80.5%  (occ 61% hurt)
//  R4: 4xfloat4 + .cs             74.7us / 81.3%  (.cs neutral)
//  R5: 2xfloat4                   73.4us / 82.8%  <- best; monotone trend:
//      shallower per-thread batch + more warp streams = better turnaround.
//  R6: endpoint of the sweep — 1 float4 per thread, 65536 blocks x 256.
//      Maximally fine-grained independent streams, ~16 regs.
//      Predicted 72.8-73.5us; if neutral, ~73us is the HW copy ceiling.
//
// 16,777,216 float4 -> 16,777,216 threads -> 65536 blocks x 256 (exact cover).

__global__ __launch_bounds__(256) void identity_copy_kernel(
    const float4* __restrict__ src, float4* __restrict__ dst)
{
    size_t i = (size_t)blockIdx.x * 256 + threadIdx.x;
    dst[i] = src[i];
}

extern "C" void kernel_launch(void* const* d_in, const int* in_sizes, int n_in,
                              void* d_out, int out_size)
{
    const float4* src = (const float4*)d_in[0];
    float4* dst = (float4*)d_out;

    identity_copy_kernel<<<65536, 256>>>(src, dst);
}

// round 12
// speedup vs baseline: 1.0008x; 1.0008x over previous
#include <cuda_runtime.h>
#include <cstdint>

// Reference = patchify ∘ depatchify == identity -> 256 MiB D2D copy.
//
// Geometry sweep (kernel time / DRAM-active):
//  MLP=8 (R3): 75.6us / 80.5%   MLP=4 (R1): 74.0us / 82.5%
//  MLP=2 (R5): 73.4us / 82.8%   <- OPTIMUM
//  MLP=1 (R6): 78.5us / 78.9%   (per-warp depth collapses)
//  CE memcpy (R2): regression.  .cs hints (R4): neutral.
//
// R7: keep the MLP=2 optimum, probe block size 512 (last orthogonal knob).
// Same per-warp access pattern, half the blocks. Expect neutral 73-74us;
// anything else confirms R5 as the hardware ceiling (~6.6 TB/s effective,
// normal HBM read/write-turnaround efficiency).
//
// 16,777,216 float4; 2 per thread -> 8,388,608 threads -> 16384 blocks x 512.
// Block b covers float4 [b*1024, (b+1)*1024); thread t touches t, t+512.

__global__ __launch_bounds__(512) void identity_copy_kernel(
    const float4* __restrict__ src, float4* __restrict__ dst)
{
    size_t base = (size_t)blockIdx.x * 1024 + threadIdx.x;

    float4 v0 = src[base];
    float4 v1 = src[base + 512];

    dst[base]       = v0;
    dst[base + 512] = v1;
}

extern "C" void kernel_launch(void* const* d_in, const int* in_sizes, int n_in,
                              void* d_out, int out_size)
{
    const float4* src = (const float4*)d_in[0];
    float4* dst = (float4*)d_out;

    identity_copy_kernel<<<16384, 512>>>(src, dst);
}